// round 7
// baseline (speedup 1.0000x reference)
#include <cuda_runtime.h>

typedef unsigned long long ULL;

// ---------------- f32x2 helpers ----------------
__device__ __forceinline__ ULL pk2(float lo, float hi) {
    ULL r; asm("mov.b64 %0, {%1,%2};" : "=l"(r) : "f"(lo), "f"(hi)); return r;
}
__device__ __forceinline__ void upk2(ULL v, float& lo, float& hi) {
    asm("mov.b64 {%0,%1}, %2;" : "=f"(lo), "=f"(hi) : "l"(v));
}
__device__ __forceinline__ ULL fma2_(ULL a, ULL b, ULL c) {
    ULL d; asm("fma.rn.f32x2 %0, %1, %2, %3;" : "=l"(d) : "l"(a), "l"(b), "l"(c)); return d;
}

// ---------------- MUFU softplus + sigmoid (scalar) ----------------
// u = exp(-|x|) via MUFU.EX2; softplus = max(x,0) + lg2(1+u)*ln2 (MUFU.LG2);
// sigmoid = (x>=0 ? 1 : u) / (1+u) via MUFU.RCP. All approx err <= ~2^-21.
__device__ __forceinline__ void act1m(float x, float& sp, float& sg) {
    float u;
    asm("ex2.approx.f32 %0, %1;" : "=f"(u)
        : "f"(fabsf(x) * -1.4426950408889634f));
    float opu = 1.0f + u;
    float lg, r;
    asm("lg2.approx.f32 %0, %1;" : "=f"(lg) : "f"(opu));
    asm("rcp.approx.f32 %0, %1;" : "=f"(r)  : "f"(opu));
    sp = fmaxf(x, 0.0f) + lg * 0.69314718055994531f;
    sg = r * ((x >= 0.0f) ? 1.0f : u);
}

// ---------------- shared-memory layout ----------------
// w2g block per jp (output pair j2=2jp, 2jp+1): 64 ulonglong2 entries,
//   index jp*64 + k2*4 + slot, slot = {P(2jp), P(2jp+1), TW(2jp), TW(2jp+1)}
//   P  = W2[j2][1+4k2 .. +3]                                 (primal)
//   TW = P * (W3[0][1+j2]*W1[k][z0] + W3[1][1+j2]*W1[k][z1]) (folded tangent+W3)
// sgA/sgB: per-thread sigmoid activations for the two samples, [k-pair][tid].
struct SmemW {
    ulonglong2 w2g[32 * 64];                     // 32768 B
    ULL sgA[32 * 128];                           // 32768 B
    ULL sgB[32 * 128];                           // 32768 B
    ULL w1t[32], w1z0[32], w1z1[32], w1b[32];    // layer-1, packed unit pairs
    ULL w2tb[64];                                // {W2[j][0], b2[j]}
    ULL w3r0[32], w3r1[32];                      // packed W3 rows
    float w3t0, w3t1, b30, b31;
};

// ---------------- one dynamics evaluation, TWO samples ----------------
__device__ __forceinline__ void eval_dyn2(SmemW& sm, int tid, float t,
    float zA0, float zA1, float zB0, float zB1,
    float& kA0, float& kA1, float& kAl,
    float& kB0, float& kB1, float& kBl)
{
    ULL s1pA[32], s1pB[32];          // packed softplus (regs); sigmoid -> smem
    ULL tp = pk2(t, t);
    ULL zA0p = pk2(zA0, zA0), zA1p = pk2(zA1, zA1);
    ULL zB0p = pk2(zB0, zB0), zB1p = pk2(zB1, zB1);
    #pragma unroll
    for (int k = 0; k < 32; ++k) {
        ULL wt = sm.w1t[k], w0 = sm.w1z0[k], w1 = sm.w1z1[k], wb = sm.w1b[k];
        ULL xA = fma2_(wt, tp, wb); xA = fma2_(w0, zA0p, xA); xA = fma2_(w1, zA1p, xA);
        ULL xB = fma2_(wt, tp, wb); xB = fma2_(w0, zB0p, xB); xB = fma2_(w1, zB1p, xB);
        float xa, xb, spa, sga, spb, sgb;
        upk2(xA, xa, xb);
        act1m(xa, spa, sga); act1m(xb, spb, sgb);
        s1pA[k] = pk2(spa, spb);
        sm.sgA[k * 128 + tid] = pk2(sga, sgb);   // private column, no sync
        upk2(xB, xa, xb);
        act1m(xa, spa, sga); act1m(xb, spb, sgb);
        s1pB[k] = pk2(spa, spb);
        sm.sgB[k * 128 + tid] = pk2(sga, sgb);
    }

    ULL ZA0 = 0ull, ZA1 = 0ull, TrA = 0ull;
    ULL ZB0 = 0ull, ZB1 = 0ull, TrB = 0ull;

    // Tile of 2 output-unit pairs (4 units); weight loads serve both samples.
    #pragma unroll 1
    for (int jt = 0; jt < 16; ++jt) {
        ULL ac[16];
        #pragma unroll
        for (int i = 0; i < 16; ++i) ac[i] = 0ull;
        const ulonglong2* rb = &sm.w2g[jt * 128];
        #pragma unroll
        for (int k2 = 0; k2 < 16; ++k2) {
            ULL seA = s1pA[2 * k2], soA = s1pA[2 * k2 + 1];
            ULL seB = s1pB[2 * k2], soB = s1pB[2 * k2 + 1];
            ULL geA = sm.sgA[(2 * k2) * 128 + tid];
            ULL goA = sm.sgA[(2 * k2 + 1) * 128 + tid];
            ULL geB = sm.sgB[(2 * k2) * 128 + tid];
            ULL goB = sm.sgB[(2 * k2 + 1) * 128 + tid];
            #pragma unroll
            for (int u = 0; u < 2; ++u) {
                const ulonglong2* r = &rb[u * 64 + k2 * 4];
                ulonglong2 P0 = r[0], P1 = r[1], T0 = r[2], T1 = r[3];
                int o = u * 8;
                ac[o+0] = fma2_(P0.x, seA, ac[o+0]); ac[o+0] = fma2_(P0.y, soA, ac[o+0]);
                ac[o+1] = fma2_(P1.x, seA, ac[o+1]); ac[o+1] = fma2_(P1.y, soA, ac[o+1]);
                ac[o+2] = fma2_(T0.x, geA, ac[o+2]); ac[o+2] = fma2_(T0.y, goA, ac[o+2]);
                ac[o+3] = fma2_(T1.x, geA, ac[o+3]); ac[o+3] = fma2_(T1.y, goA, ac[o+3]);
                ac[o+4] = fma2_(P0.x, seB, ac[o+4]); ac[o+4] = fma2_(P0.y, soB, ac[o+4]);
                ac[o+5] = fma2_(P1.x, seB, ac[o+5]); ac[o+5] = fma2_(P1.y, soB, ac[o+5]);
                ac[o+6] = fma2_(T0.x, geB, ac[o+6]); ac[o+6] = fma2_(T0.y, goB, ac[o+6]);
                ac[o+7] = fma2_(T1.x, geB, ac[o+7]); ac[o+7] = fma2_(T1.y, goB, ac[o+7]);
            }
        }
        #pragma unroll
        for (int u = 0; u < 2; ++u) {
            int jp = 2 * jt + u;
            int o = u * 8;
            float w2ta, b2a; upk2(sm.w2tb[2 * jp],     w2ta, b2a);
            float w2tc, b2c; upk2(sm.w2tb[2 * jp + 1], w2tc, b2c);
            float pl, ph;
            upk2(ac[o+0], pl, ph); float hA0  = pl + ph + fmaf(w2ta, t, b2a);
            upk2(ac[o+1], pl, ph); float hA1  = pl + ph + fmaf(w2tc, t, b2c);
            upk2(ac[o+2], pl, ph); float tdA0 = pl + ph;
            upk2(ac[o+3], pl, ph); float tdA1 = pl + ph;
            upk2(ac[o+4], pl, ph); float hB0  = pl + ph + fmaf(w2ta, t, b2a);
            upk2(ac[o+5], pl, ph); float hB1  = pl + ph + fmaf(w2tc, t, b2c);
            upk2(ac[o+6], pl, ph); float tdB0 = pl + ph;
            upk2(ac[o+7], pl, ph); float tdB1 = pl + ph;
            float sA0, gA0, sA1, gA1, sB0, gB0, sB1, gB1;
            act1m(hA0, sA0, gA0); act1m(hA1, sA1, gA1);
            act1m(hB0, sB0, gB0); act1m(hB1, sB1, gB1);
            ULL w30 = sm.w3r0[jp], w31 = sm.w3r1[jp];
            ULL spA = pk2(sA0, sA1), spB = pk2(sB0, sB1);
            ZA0 = fma2_(w30, spA, ZA0);
            ZA1 = fma2_(w31, spA, ZA1);
            TrA = fma2_(pk2(gA0, gA1), pk2(tdA0, tdA1), TrA);
            ZB0 = fma2_(w30, spB, ZB0);
            ZB1 = fma2_(w31, spB, ZB1);
            TrB = fma2_(pk2(gB0, gB1), pk2(tdB0, tdB1), TrB);
        }
    }
    float a, b;
    float bias0 = fmaf(sm.w3t0, t, sm.b30);
    float bias1 = fmaf(sm.w3t1, t, sm.b31);
    upk2(ZA0, a, b); kA0 = a + b + bias0;
    upk2(ZA1, a, b); kA1 = a + b + bias1;
    upk2(TrA, a, b); kAl = -(a + b);
    upk2(ZB0, a, b); kB0 = a + b + bias0;
    upk2(ZB1, a, b); kB1 = a + b + bias1;
    upk2(TrB, a, b); kBl = -(a + b);
}

__global__ void __launch_bounds__(128, 2) ffjord_kernel(
    const float2* __restrict__ zin, const float* __restrict__ dlp,
    const float* __restrict__ W1, const float* __restrict__ b1,
    const float* __restrict__ W2, const float* __restrict__ b2,
    const float* __restrict__ W3, const float* __restrict__ b3,
    float* __restrict__ out, int B)
{
    extern __shared__ unsigned char smraw[];
    SmemW& sm = *reinterpret_cast<SmemW*>(smraw);
    int tid = threadIdx.x;

    // ---- stage weights into smem ----
    for (int idx = tid; idx < 2048; idx += 128) {
        int jp   = idx >> 6;
        int rem  = idx & 63;
        int k2   = rem >> 2;
        int slot = rem & 3;
        int j2   = 2 * jp + (slot & 1);
        int bb   = 4 * k2;
        const float* wr = W2 + j2 * 65 + 1;          // skip time column
        float p0 = wr[bb + 0], p1 = wr[bb + 1], p2 = wr[bb + 2], p3 = wr[bb + 3];
        ulonglong2 E;
        if (slot < 2) {
            E.x = pk2(p0, p1); E.y = pk2(p2, p3);
        } else {
            float w30 = W3[1 + j2], w31 = W3[66 + j2];
            float t0 = fmaf(w30, W1[(bb + 0) * 3 + 1], w31 * W1[(bb + 0) * 3 + 2]);
            float t1 = fmaf(w30, W1[(bb + 1) * 3 + 1], w31 * W1[(bb + 1) * 3 + 2]);
            float t2 = fmaf(w30, W1[(bb + 2) * 3 + 1], w31 * W1[(bb + 2) * 3 + 2]);
            float t3 = fmaf(w30, W1[(bb + 3) * 3 + 1], w31 * W1[(bb + 3) * 3 + 2]);
            E.x = pk2(p0 * t0, p1 * t1); E.y = pk2(p2 * t2, p3 * t3);
        }
        sm.w2g[idx] = E;
    }
    if (tid < 32) {
        int k = tid;                                  // unit pair (2k, 2k+1)
        sm.w1t[k]  = pk2(W1[(2 * k) * 3 + 0], W1[(2 * k + 1) * 3 + 0]);
        sm.w1z0[k] = pk2(W1[(2 * k) * 3 + 1], W1[(2 * k + 1) * 3 + 1]);
        sm.w1z1[k] = pk2(W1[(2 * k) * 3 + 2], W1[(2 * k + 1) * 3 + 2]);
        sm.w1b[k]  = pk2(b1[2 * k], b1[2 * k + 1]);
        sm.w3r0[k] = pk2(W3[1 + 2 * k],  W3[2 + 2 * k]);
        sm.w3r1[k] = pk2(W3[66 + 2 * k], W3[67 + 2 * k]);
    } else if (tid < 96) {
        int j = tid - 32;
        sm.w2tb[j] = pk2(W2[j * 65 + 0], b2[j]);
    }
    if (tid == 0) { sm.w3t0 = W3[0]; sm.w3t1 = W3[65]; sm.b30 = b3[0]; sm.b31 = b3[1]; }
    __syncthreads();

    int half = B >> 1;
    int gid = blockIdx.x * 128 + tid;
    if (gid >= half) return;
    int gidB = gid + half;

    float2 zvA = zin[gid];
    float2 zvB = zin[gidB];
    float zA0 = zvA.x, zA1 = zvA.y, lpA = dlp[gid];
    float zB0 = zvB.x, zB1 = zvB.y, lpB = dlp[gidB];

    const float dt = 0.25f;
    #pragma unroll 1
    for (int step = 0; step < 4; ++step) {
        float tb = (float)step * dt;
        float aA0 = 0.f, aA1 = 0.f, aAl = 0.f;
        float aB0 = 0.f, aB1 = 0.f, aBl = 0.f;
        float pA0 = 0.f, pA1 = 0.f, pB0 = 0.f, pB1 = 0.f;
        #pragma unroll 1
        for (int s = 0; s < 4; ++s) {
            float cs = (s == 0) ? 0.0f : ((s == 3) ? dt : 0.5f * dt);
            float ws = (s == 1 || s == 2) ? 2.0f : 1.0f;
            float te = tb + cs;
            float iA0 = fmaf(cs, pA0, zA0), iA1 = fmaf(cs, pA1, zA1);
            float iB0 = fmaf(cs, pB0, zB0), iB1 = fmaf(cs, pB1, zB1);
            float kA0, kA1, kAl, kB0, kB1, kBl;
            eval_dyn2(sm, tid, te, iA0, iA1, iB0, iB1,
                      kA0, kA1, kAl, kB0, kB1, kBl);
            aA0 = fmaf(ws, kA0, aA0); aA1 = fmaf(ws, kA1, aA1); aAl = fmaf(ws, kAl, aAl);
            aB0 = fmaf(ws, kB0, aB0); aB1 = fmaf(ws, kB1, aB1); aBl = fmaf(ws, kBl, aBl);
            pA0 = kA0; pA1 = kA1; pB0 = kB0; pB1 = kB1;
        }
        const float c6 = dt / 6.0f;
        zA0 = fmaf(c6, aA0, zA0); zA1 = fmaf(c6, aA1, zA1); lpA = fmaf(c6, aAl, lpA);
        zB0 = fmaf(c6, aB0, zB0); zB1 = fmaf(c6, aB1, zB1); lpB = fmaf(c6, aBl, lpB);
    }

    reinterpret_cast<float2*>(out)[gid]  = make_float2(zA0, zA1);
    reinterpret_cast<float2*>(out)[gidB] = make_float2(zB0, zB1);
    out[2 * B + gid]  = lpA;
    out[2 * B + gidB] = lpB;
}

extern "C" void kernel_launch(void* const* d_in, const int* in_sizes, int n_in,
                              void* d_out, int out_size) {
    const float2* z  = (const float2*)d_in[0];
    const float* dlp = (const float*)d_in[1];
    const float* W1  = (const float*)d_in[2];
    const float* b1  = (const float*)d_in[3];
    const float* W2  = (const float*)d_in[4];
    const float* b2  = (const float*)d_in[5];
    const float* W3  = (const float*)d_in[6];
    const float* b3  = (const float*)d_in[7];
    float* out = (float*)d_out;
    int B = in_sizes[0] / 2;

    // Host-side, enqueues nothing -> graph-capture safe. Idempotent.
    cudaFuncSetAttribute(ffjord_kernel, cudaFuncAttributeMaxDynamicSharedMemorySize,
                         (int)sizeof(SmemW));

    int half = B / 2;
    int blocks = (half + 127) / 128;
    ffjord_kernel<<<blocks, 128, sizeof(SmemW)>>>(z, dlp, W1, b1, W2, b2, W3, b3, out, B);
}

// round 8
// speedup vs baseline: 2.1677x; 2.1677x over previous
#include <cuda_runtime.h>

typedef unsigned long long ULL;

// ---------------- f32x2 helpers ----------------
__device__ __forceinline__ ULL pk2(float lo, float hi) {
    ULL r; asm("mov.b64 %0, {%1,%2};" : "=l"(r) : "f"(lo), "f"(hi)); return r;
}
__device__ __forceinline__ void upk2(ULL v, float& lo, float& hi) {
    asm("mov.b64 {%0,%1}, %2;" : "=f"(lo), "=f"(hi) : "l"(v));
}
__device__ __forceinline__ ULL fma2_(ULL a, ULL b, ULL c) {
    ULL d; asm("fma.rn.f32x2 %0, %1, %2, %3;" : "=l"(d) : "l"(a), "l"(b), "l"(c)); return d;
}

// ---------------- MUFU softplus + sigmoid (scalar) ----------------
// u = exp(-|x|) via MUFU.EX2; softplus = max(x,0) + lg2(1+u)*ln2 (MUFU.LG2);
// sigmoid = (x>=0 ? 1 : u) / (1+u) via MUFU.RCP. All approx err <= ~2^-21.
__device__ __forceinline__ void act1m(float x, float& sp, float& sg) {
    float u;
    asm("ex2.approx.f32 %0, %1;" : "=f"(u)
        : "f"(fabsf(x) * -1.4426950408889634f));
    float opu = 1.0f + u;
    float lg, r;
    asm("lg2.approx.f32 %0, %1;" : "=f"(lg) : "f"(opu));
    asm("rcp.approx.f32 %0, %1;" : "=f"(r)  : "f"(opu));
    sp = fmaxf(x, 0.0f) + lg * 0.69314718055994531f;
    sg = r * ((x >= 0.0f) ? 1.0f : u);
}

// ---------------- shared-memory layout ----------------
// w2g block per jp (output pair j2=2jp, 2jp+1): 64 ulonglong2 entries,
//   index jp*64 + k2*4 + slot, slot = {P(2jp), P(2jp+1), TW(2jp), TW(2jp+1)}
//   P  = W2[j2][1+4k2 .. +3]                                 (primal)
//   TW = P * (W3[0][1+j2]*W1[k][z0] + W3[1][1+j2]*W1[k][z1]) (folded tangent+W3)
// actsg: per-thread sigmoid activations [k-pair][tid], conflict-free LDS.64.
struct SmemW {
    ulonglong2 w2g[32 * 64];                     // 32768 B
    ULL actsg[32 * 128];                         // 32768 B (per-thread scratch)
    ULL w1t[32], w1z0[32], w1z1[32], w1b[32];    // layer-1, packed unit pairs
    ULL w2tb[64];                                // {W2[j][0], b2[j]}
    ULL w3r0[32], w3r1[32];                      // packed W3 rows (z_dot epilogue)
    float w3t0, w3t1, b30, b31;
};

// ---------------- one dynamics evaluation ----------------
__device__ __forceinline__ void eval_dyn(SmemW& sm, int tid, float t, float z0, float z1,
                                         float& k0, float& k1, float& kl)
{
    ULL s1p[32];            // packed softplus of layer-1 (regs); sigmoid -> smem
    ULL tp = pk2(t, t), z0p = pk2(z0, z0), z1p = pk2(z1, z1);
    #pragma unroll
    for (int k = 0; k < 32; ++k) {
        ULL x = fma2_(sm.w1t[k], tp, sm.w1b[k]);
        x = fma2_(sm.w1z0[k], z0p, x);
        x = fma2_(sm.w1z1[k], z1p, x);
        float xa, xb; upk2(x, xa, xb);
        float spa, sga, spb, sgb;
        act1m(xa, spa, sga);
        act1m(xb, spb, sgb);
        s1p[k] = pk2(spa, spb);
        sm.actsg[k * 128 + tid] = pk2(sga, sgb);   // private column, no sync
    }

    ULL Zd0 = 0ull, Zd1 = 0ull, Tr = 0ull;   // bit pattern 0 == {0.f, 0.f}

    // Tile of 4 output-unit pairs (8 units): activation loads amortized x4.
    #pragma unroll 1
    for (int jt = 0; jt < 8; ++jt) {
        ULL accp[8], acct[8];
        #pragma unroll
        for (int u = 0; u < 8; ++u) { accp[u] = 0ull; acct[u] = 0ull; }
        const ulonglong2* rb = &sm.w2g[jt * 256];
        #pragma unroll
        for (int k2 = 0; k2 < 16; ++k2) {
            ULL se = s1p[2 * k2], so = s1p[2 * k2 + 1];
            ULL ge = sm.actsg[(2 * k2) * 128 + tid];
            ULL go = sm.actsg[(2 * k2 + 1) * 128 + tid];
            #pragma unroll
            for (int u = 0; u < 4; ++u) {
                const ulonglong2* r = &rb[u * 64 + k2 * 4];
                ulonglong2 P0 = r[0];
                ulonglong2 P1 = r[1];
                ulonglong2 T0 = r[2];
                ulonglong2 T1 = r[3];
                accp[2*u]   = fma2_(P0.x, se, accp[2*u]);
                accp[2*u]   = fma2_(P0.y, so, accp[2*u]);
                accp[2*u+1] = fma2_(P1.x, se, accp[2*u+1]);
                accp[2*u+1] = fma2_(P1.y, so, accp[2*u+1]);
                acct[2*u]   = fma2_(T0.x, ge, acct[2*u]);
                acct[2*u]   = fma2_(T0.y, go, acct[2*u]);
                acct[2*u+1] = fma2_(T1.x, ge, acct[2*u+1]);
                acct[2*u+1] = fma2_(T1.y, go, acct[2*u+1]);
            }
        }
        #pragma unroll
        for (int u = 0; u < 4; ++u) {
            int jp = jt * 4 + u;
            float w2ta, b2a; upk2(sm.w2tb[2 * jp],     w2ta, b2a);
            float w2tc, b2c; upk2(sm.w2tb[2 * jp + 1], w2tc, b2c);
            float pl, ph;
            upk2(accp[2*u],   pl, ph); float h20 = pl + ph + fmaf(w2ta, t, b2a);
            upk2(accp[2*u+1], pl, ph); float h21 = pl + ph + fmaf(w2tc, t, b2c);
            upk2(acct[2*u],   pl, ph); float td0 = pl + ph;
            upk2(acct[2*u+1], pl, ph); float td1 = pl + ph;
            float sp0, sg0, sp1, sg1;
            act1m(h20, sp0, sg0);
            act1m(h21, sp1, sg1);
            ULL sp2 = pk2(sp0, sp1);
            Zd0 = fma2_(sm.w3r0[jp], sp2, Zd0);
            Zd1 = fma2_(sm.w3r1[jp], sp2, Zd1);
            Tr  = fma2_(pk2(sg0, sg1), pk2(td0, td1), Tr);
        }
    }
    float a, b;
    upk2(Zd0, a, b); k0 = a + b + fmaf(sm.w3t0, t, sm.b30);
    upk2(Zd1, a, b); k1 = a + b + fmaf(sm.w3t1, t, sm.b31);
    upk2(Tr,  a, b); kl = -(a + b);
}

__global__ void __launch_bounds__(128, 3) ffjord_kernel(
    const float2* __restrict__ zin, const float* __restrict__ dlp,
    const float* __restrict__ W1, const float* __restrict__ b1,
    const float* __restrict__ W2, const float* __restrict__ b2,
    const float* __restrict__ W3, const float* __restrict__ b3,
    float* __restrict__ out, int B)
{
    extern __shared__ unsigned char smraw[];
    SmemW& sm = *reinterpret_cast<SmemW*>(smraw);
    int tid = threadIdx.x;

    // ---- stage weights into smem ----
    for (int idx = tid; idx < 2048; idx += 128) {
        int jp   = idx >> 6;
        int rem  = idx & 63;
        int k2   = rem >> 2;
        int slot = rem & 3;
        int j2   = 2 * jp + (slot & 1);
        int bb   = 4 * k2;
        const float* wr = W2 + j2 * 65 + 1;          // skip time column
        float p0 = wr[bb + 0], p1 = wr[bb + 1], p2 = wr[bb + 2], p3 = wr[bb + 3];
        ulonglong2 E;
        if (slot < 2) {
            E.x = pk2(p0, p1); E.y = pk2(p2, p3);
        } else {
            float w30 = W3[1 + j2], w31 = W3[66 + j2];
            float t0 = fmaf(w30, W1[(bb + 0) * 3 + 1], w31 * W1[(bb + 0) * 3 + 2]);
            float t1 = fmaf(w30, W1[(bb + 1) * 3 + 1], w31 * W1[(bb + 1) * 3 + 2]);
            float t2 = fmaf(w30, W1[(bb + 2) * 3 + 1], w31 * W1[(bb + 2) * 3 + 2]);
            float t3 = fmaf(w30, W1[(bb + 3) * 3 + 1], w31 * W1[(bb + 3) * 3 + 2]);
            E.x = pk2(p0 * t0, p1 * t1); E.y = pk2(p2 * t2, p3 * t3);
        }
        sm.w2g[idx] = E;
    }
    if (tid < 32) {
        int k = tid;                                  // unit pair (2k, 2k+1)
        sm.w1t[k]  = pk2(W1[(2 * k) * 3 + 0], W1[(2 * k + 1) * 3 + 0]);
        sm.w1z0[k] = pk2(W1[(2 * k) * 3 + 1], W1[(2 * k + 1) * 3 + 1]);
        sm.w1z1[k] = pk2(W1[(2 * k) * 3 + 2], W1[(2 * k + 1) * 3 + 2]);
        sm.w1b[k]  = pk2(b1[2 * k], b1[2 * k + 1]);
        sm.w3r0[k] = pk2(W3[1 + 2 * k],  W3[2 + 2 * k]);
        sm.w3r1[k] = pk2(W3[66 + 2 * k], W3[67 + 2 * k]);
    } else if (tid < 96) {
        int j = tid - 32;
        sm.w2tb[j] = pk2(W2[j * 65 + 0], b2[j]);
    }
    if (tid == 0) { sm.w3t0 = W3[0]; sm.w3t1 = W3[65]; sm.b30 = b3[0]; sm.b31 = b3[1]; }
    __syncthreads();

    int gid = blockIdx.x * 128 + tid;
    if (gid >= B) return;
    float2 zv = zin[gid];
    float z0 = zv.x, z1 = zv.y;
    float lp = dlp[gid];

    const float dt = 0.25f;
    #pragma unroll 1
    for (int step = 0; step < 4; ++step) {
        float tb = (float)step * dt;
        float acc0 = 0.0f, acc1 = 0.0f, accl = 0.0f;
        float pk0v = 0.0f, pk1v = 0.0f;
        #pragma unroll 1
        for (int s = 0; s < 4; ++s) {
            float cs = (s == 0) ? 0.0f : ((s == 3) ? dt : 0.5f * dt);
            float ws = (s == 1 || s == 2) ? 2.0f : 1.0f;
            float te = tb + cs;
            float i0 = fmaf(cs, pk0v, z0);
            float i1 = fmaf(cs, pk1v, z1);
            float k0, k1, klv;
            eval_dyn(sm, tid, te, i0, i1, k0, k1, klv);
            acc0 = fmaf(ws, k0, acc0);
            acc1 = fmaf(ws, k1, acc1);
            accl = fmaf(ws, klv, accl);
            pk0v = k0; pk1v = k1;
        }
        const float c6 = dt / 6.0f;
        z0 = fmaf(c6, acc0, z0);
        z1 = fmaf(c6, acc1, z1);
        lp = fmaf(c6, accl, lp);
    }

    reinterpret_cast<float2*>(out)[gid] = make_float2(z0, z1);  // zf: (B,2)
    out[2 * B + gid] = lp;                                      // delta_logpz: (B,1)
}

extern "C" void kernel_launch(void* const* d_in, const int* in_sizes, int n_in,
                              void* d_out, int out_size) {
    const float2* z  = (const float2*)d_in[0];
    const float* dlp = (const float*)d_in[1];
    const float* W1  = (const float*)d_in[2];
    const float* b1  = (const float*)d_in[3];
    const float* W2  = (const float*)d_in[4];
    const float* b2  = (const float*)d_in[5];
    const float* W3  = (const float*)d_in[6];
    const float* b3  = (const float*)d_in[7];
    float* out = (float*)d_out;
    int B = in_sizes[0] / 2;

    // Host-side, enqueues nothing -> graph-capture safe. Idempotent.
    cudaFuncSetAttribute(ffjord_kernel, cudaFuncAttributeMaxDynamicSharedMemorySize,
                         (int)sizeof(SmemW));

    int blocks = (B + 127) / 128;
    ffjord_kernel<<<blocks, 128, sizeof(SmemW)>>>(z, dlp, W1, b1, W2, b2, W3, b3, out, B);
}